// round 14
// baseline (speedup 1.0000x reference)
#include <cuda_runtime.h>
#include <cuda_bf16.h>
#include <mma.h>
#include <cstdint>

using namespace nvcuda;

#define B_  64
#define T_  2048
#define I_  256
#define H_  256
#define G3_ 768

// 402 MB scratch for precomputed input gates (NO bias): layout [t][b][768]
__device__ float g_Gi[(size_t)B_ * T_ * G3_];

// ======================= Phase 1: Gi = x @ W_ih^T  (wmma bf16 hi/lo) ==========
// (unchanged from R9 — measured ~460 us, rel_err contribution ~4e-6)

#define GBK 32
#define GLD 48

__global__ __launch_bounds__(256) void gi_gemm_wmma(
    const float* __restrict__ x, const float* __restrict__ W_ih,
    const int* __restrict__ lengths)
{
    const int mt    = blockIdx.x;
    const int batch = mt >> 4;
    const int t0    = (mt & 15) * 128;
    if (t0 >= __ldg(&lengths[batch])) return;
    const int n0 = blockIdx.y * 64;

    __shared__ __nv_bfloat16 Ah[128][GLD], Al[128][GLD];
    __shared__ __nv_bfloat16 Bh[64][GLD],  Bl[64][GLD];

    const int tid  = threadIdx.x;
    const int warp = tid >> 5;
    const int wm   = warp >> 1;
    const int wn   = warp & 1;

    wmma::fragment<wmma::accumulator, 16, 16, 16, float> acc[2][2];
#pragma unroll
    for (int mi = 0; mi < 2; mi++)
#pragma unroll
        for (int ni = 0; ni < 2; ni++) wmma::fill_fragment(acc[mi][ni], 0.f);

    for (int ks = 0; ks < I_; ks += GBK) {
#pragma unroll
        for (int j = 0; j < 4; j++) {
            const int idx = tid + j * 256;
            const int row = idx >> 3, c = (idx & 7) * 4;
            float4 v = *(const float4*)&x[(size_t)(batch * T_ + t0 + row) * I_ + ks + c];
            __nv_bfloat16 hx = __float2bfloat16(v.x);
            __nv_bfloat16 hy = __float2bfloat16(v.y);
            __nv_bfloat16 hz = __float2bfloat16(v.z);
            __nv_bfloat16 hw = __float2bfloat16(v.w);
            *(__nv_bfloat162*)&Ah[row][c]     = __nv_bfloat162(hx, hy);
            *(__nv_bfloat162*)&Ah[row][c + 2] = __nv_bfloat162(hz, hw);
            *(__nv_bfloat162*)&Al[row][c] = __nv_bfloat162(
                __float2bfloat16(v.x - __bfloat162float(hx)),
                __float2bfloat16(v.y - __bfloat162float(hy)));
            *(__nv_bfloat162*)&Al[row][c + 2] = __nv_bfloat162(
                __float2bfloat16(v.z - __bfloat162float(hz)),
                __float2bfloat16(v.w - __bfloat162float(hw)));
        }
#pragma unroll
        for (int j = 0; j < 2; j++) {
            const int idx = tid + j * 256;
            const int row = idx >> 3, c = (idx & 7) * 4;
            float4 v = *(const float4*)&W_ih[(size_t)(n0 + row) * I_ + ks + c];
            __nv_bfloat16 hx = __float2bfloat16(v.x);
            __nv_bfloat16 hy = __float2bfloat16(v.y);
            __nv_bfloat16 hz = __float2bfloat16(v.z);
            __nv_bfloat16 hw = __float2bfloat16(v.w);
            *(__nv_bfloat162*)&Bh[row][c]     = __nv_bfloat162(hx, hy);
            *(__nv_bfloat162*)&Bh[row][c + 2] = __nv_bfloat162(hz, hw);
            *(__nv_bfloat162*)&Bl[row][c] = __nv_bfloat162(
                __float2bfloat16(v.x - __bfloat162float(hx)),
                __float2bfloat16(v.y - __bfloat162float(hy)));
            *(__nv_bfloat162*)&Bl[row][c + 2] = __nv_bfloat162(
                __float2bfloat16(v.z - __bfloat162float(hz)),
                __float2bfloat16(v.w - __bfloat162float(hw)));
        }
        __syncthreads();

#pragma unroll
        for (int kk = 0; kk < GBK; kk += 16) {
            wmma::fragment<wmma::matrix_a, 16, 16, 16, __nv_bfloat16,
                           wmma::row_major> ah[2], al[2];
            wmma::fragment<wmma::matrix_b, 16, 16, 16, __nv_bfloat16,
                           wmma::col_major> bh[2], bl[2];
#pragma unroll
            for (int mi = 0; mi < 2; mi++) {
                wmma::load_matrix_sync(ah[mi], &Ah[wm * 32 + mi * 16][kk], GLD);
                wmma::load_matrix_sync(al[mi], &Al[wm * 32 + mi * 16][kk], GLD);
            }
#pragma unroll
            for (int ni = 0; ni < 2; ni++) {
                wmma::load_matrix_sync(bh[ni], &Bh[wn * 32 + ni * 16][kk], GLD);
                wmma::load_matrix_sync(bl[ni], &Bl[wn * 32 + ni * 16][kk], GLD);
            }
#pragma unroll
            for (int mi = 0; mi < 2; mi++)
#pragma unroll
                for (int ni = 0; ni < 2; ni++) {
                    wmma::mma_sync(acc[mi][ni], ah[mi], bh[ni], acc[mi][ni]);
                    wmma::mma_sync(acc[mi][ni], ah[mi], bl[ni], acc[mi][ni]);
                    wmma::mma_sync(acc[mi][ni], al[mi], bh[ni], acc[mi][ni]);
                }
        }
        __syncthreads();
    }

#pragma unroll
    for (int mi = 0; mi < 2; mi++)
#pragma unroll
        for (int ni = 0; ni < 2; ni++) {
            float* dst = &g_Gi[((size_t)(t0 + wm * 32 + mi * 16) * B_ + batch) * G3_
                               + n0 + wn * 32 + ni * 16];
            wmma::store_matrix_sync(dst, acc[mi][ni], (unsigned)(B_ * G3_),
                                    wmma::mem_row_major);
        }
}

// ======================= Phase 2: recurrence (HMMA matvec) ====================
// R13 structure. R14 change: h exchange messages widened 8 B -> 16 B
// (st.async.v4.b32, one sender lane per 4 columns). Bytes unchanged (4 KB,
// EXP_TX same); messages per receiving CTA drop 512 -> 128 — tests the
// DSMEM/mbarrier ingress-serialization theory for the ~1800 unmodeled
// cycles/step. Receiver hx layout is byte-identical.

#define REC_THREADS 768
#define EXP_TX 4096
#define HXW 1056                         // 4 batches * 264 words

__device__ __forceinline__ float sigm(float v) { return 1.f / (1.f + __expf(-v)); }
__device__ __forceinline__ float tanh_fast(float u) {
    const float t = __expf(-2.f * fabsf(u));
    const float m = (1.f - t) / (1.f + t);
    return copysignf(m, u);
}
__device__ __forceinline__ uint32_t split_pack(float2 v, uint32_t& lo_pack) {
    uint16_t h0, h1, l0, l1;
    asm("cvt.rn.bf16.f32 %0, %1;" : "=h"(h0) : "f"(v.x));
    asm("cvt.rn.bf16.f32 %0, %1;" : "=h"(h1) : "f"(v.y));
    float r0 = v.x - __uint_as_float((uint32_t)h0 << 16);
    float r1 = v.y - __uint_as_float((uint32_t)h1 << 16);
    asm("cvt.rn.bf16.f32 %0, %1;" : "=h"(l0) : "f"(r0));
    asm("cvt.rn.bf16.f32 %0, %1;" : "=h"(l1) : "f"(r1));
    lo_pack = (uint32_t)l0 | ((uint32_t)l1 << 16);
    return (uint32_t)h0 | ((uint32_t)h1 << 16);
}
__device__ __forceinline__ void mma_bf16(
    float& c0, float& c1, float& c2, float& c3,
    uint32_t a0, uint32_t a1, uint32_t a2, uint32_t a3,
    uint32_t b0, uint32_t b1)
{
    asm("mma.sync.aligned.m16n8k16.row.col.f32.bf16.bf16.f32 "
        "{%0,%1,%2,%3}, {%4,%5,%6,%7}, {%8,%9}, {%0,%1,%2,%3};"
        : "+f"(c0), "+f"(c1), "+f"(c2), "+f"(c3)
        : "r"(a0), "r"(a1), "r"(a2), "r"(a3), "r"(b0), "r"(b1));
}
__device__ __forceinline__ uint32_t prmt(uint32_t a, uint32_t b, uint32_t s) {
    uint32_t d;
    asm("prmt.b32 %0, %1, %2, %3;" : "=r"(d) : "r"(a), "r"(b), "r"(s));
    return d;
}
__device__ __forceinline__ void mbar_wait(uint32_t mbar, uint32_t parity) {
    uint32_t done;
    asm volatile(
        "{\n\t.reg .pred p;\n\t"
        "mbarrier.try_wait.parity.acquire.cta.shared::cta.b64 p, [%1], %2;\n\t"
        "selp.b32 %0, 1, 0, p;\n\t}"
        : "=r"(done) : "r"(mbar), "r"(parity) : "memory");
    while (!done) {
        asm volatile(
            "{\n\t.reg .pred p;\n\t"
            "mbarrier.try_wait.parity.acquire.cta.shared::cta.b64 p, [%1], %2, 0x989680;\n\t"
            "selp.b32 %0, 1, 0, p;\n\t}"
            : "=r"(done) : "r"(mbar), "r"(parity) : "memory");
    }
}

__global__ void __cluster_dims__(8, 1, 1) __launch_bounds__(REC_THREADS, 1)
gru_rec(const float* __restrict__ att, const int* __restrict__ lengths,
        const float* __restrict__ W_hh, const float* __restrict__ b_hh,
        const float* __restrict__ b_ih, float* __restrict__ out)
{
    __shared__ alignas(16) uint32_t hx[2][HXW];  // [buf][b*264 + pair*2 + sel]
    __shared__ float ghp[4][4][104];             // [kc][batch][row 0..95, pad]
    __shared__ alignas(8) unsigned long long mbar[2];

    uint32_t rank;
    asm("mov.u32 %0, %%cluster_ctarank;" : "=r"(rank));
    const int cid = blockIdx.x >> 3;
    const int b0  = cid * 4;

    const int tid  = threadIdx.x;
    const int warp = tid >> 5;
    const int lane = tid & 31;
    const int m    = warp >> 2;           // m-tile 0..5
    const int kc   = warp & 3;            // k slice 0..3
    const int q    = lane & 3;
    const int rg2  = lane >> 2;           // 0..7

    // ---- loop-invariant A fragments (W_hh hi/lo) ----
    const int row0 = m * 16 + rg2;                               // local row
    const int grow = (row0 >> 5) * 256 + (int)rank * 32 + (row0 & 31);
    uint32_t ahi[4][4], alo[4][4];
#pragma unroll
    for (int ks = 0; ks < 4; ks++) {
        const int k0 = kc * 64 + ks * 16 + q * 2;
        float2 v00 = *(const float2*)&W_hh[(size_t)grow * H_ + k0];
        float2 v10 = *(const float2*)&W_hh[(size_t)(grow + 8) * H_ + k0];
        float2 v01 = *(const float2*)&W_hh[(size_t)grow * H_ + k0 + 8];
        float2 v11 = *(const float2*)&W_hh[(size_t)(grow + 8) * H_ + k0 + 8];
        ahi[ks][0] = split_pack(v00, alo[ks][0]);
        ahi[ks][1] = split_pack(v10, alo[ks][1]);
        ahi[ks][2] = split_pack(v01, alo[ks][2]);
        ahi[ks][3] = split_pack(v11, alo[ks][3]);
    }

    // ---- zero h buffer 0, init mbarriers ----
    for (int i = tid; i < HXW; i += REC_THREADS) hx[0][i] = 0u;
    if (tid < 2) {
        uint32_t mb = (uint32_t)__cvta_generic_to_shared(&mbar[tid]);
        asm volatile("mbarrier.init.shared.b64 [%0], 1;" :: "r"(mb) : "memory");
    }

    // ---- gate constants (threads 0..127: gb = tid>>5, gj = tid&31) ----
    const int gb   = tid >> 5;
    const int gj   = tid & 31;
    const int col  = (int)rank * 32 + gj;
    const int myb  = b0 + gb;
    float bcr = 0.f, bcz = 0.f, bcn = 0.f, bhn = 0.f;
    int mylen = 0;
    if (tid < 128) {
        bcr = b_ih[col] + b_hh[col];
        bcz = b_ih[256 + col] + b_hh[256 + col];
        bcn = b_ih[512 + col];
        bhn = b_hh[512 + col];
        mylen = lengths[myb];
    }
    float hreg = 0.f;
    const int Tmax = max(max(__ldg(&lengths[b0]),     __ldg(&lengths[b0 + 1])),
                         max(__ldg(&lengths[b0 + 2]), __ldg(&lengths[b0 + 3])));

    // ---- lane constants for B-fragment loads ----
    const int wb = (lane >> 3) * 264 + kc * 64 + q * 2 + ((lane >> 2) & 1);

    // ---- hoisted peer addresses (sending lanes: tid<128, gj%4==0) ----
    // rh0[d] = peer-d address of our 16 B hx[0] slot (pairs gj/2, gj/2+1);
    // buffer/mbar variants are constant intra-CTA deltas.
    uint32_t rh0[8];
    int32_t  dmb = 0;
    {
        const int pair = (int)rank * 16 + (gj >> 1);
        uint32_t lh0 = (uint32_t)__cvta_generic_to_shared(&hx[0][gb * 264 + pair * 2]);
        uint32_t lm0 = (uint32_t)__cvta_generic_to_shared(&mbar[0]);
        dmb = (int32_t)(lm0 - lh0);
#pragma unroll
        for (int d = 0; d < 8; d++)
            asm("mapa.shared::cluster.u32 %0, %1, %2;"
                : "=r"(rh0[d]) : "r"(lh0), "r"(d));
    }

    __syncthreads();
    asm volatile("barrier.cluster.arrive.aligned;" ::: "memory");
    asm volatile("barrier.cluster.wait.aligned;" ::: "memory");

    uint32_t ph0 = 0, ph1 = 0;

    for (int t = 0; t < Tmax; t++) {
        const int cur = t & 1, nxt = cur ^ 1;

        // arm next buffer (non-gate warp)
        if (tid == 256) {
            uint32_t mn = (uint32_t)__cvta_generic_to_shared(&mbar[nxt]);
            asm volatile("mbarrier.arrive.expect_tx.shared.b64 _, [%0], %1;"
                         :: "r"(mn), "n"(EXP_TX) : "memory");
        }

        // gi prefetch + bias fold (no h dependency)
        float gir = 0.f, giz = 0.f, gin = 0.f, wt = 0.f;
        if (tid < 128) {
            const size_t base = ((size_t)t * B_ + myb) * G3_;
            gir = __ldg(&g_Gi[base + col]) + bcr;
            giz = __ldg(&g_Gi[base + 256 + col]) + bcz;
            gin = __ldg(&g_Gi[base + 512 + col]) + bcn;
            wt  = __ldg(&att[(size_t)myb * T_ + t]);
        }

        if (t > 0) {
            uint32_t mc = (uint32_t)__cvta_generic_to_shared(&mbar[cur]);
            mbar_wait(mc, cur ? ph1 : ph0);
            if (cur) ph1 ^= 1; else ph0 ^= 1;
        }

        // ---- HMMA matvec: dual independent chains (hi->c, lo->d) ----
        float c0 = 0.f, c1 = 0.f, c2 = 0.f, c3 = 0.f;
        float d0 = 0.f, d1 = 0.f, d2 = 0.f, d3 = 0.f;
        {
            const uint32_t* hxc = hx[cur];
#pragma unroll
            for (int ks = 0; ks < 4; ks++) {
                const uint32_t bf0 = hxc[wb + ks * 16];
                const uint32_t bf1 = hxc[wb + ks * 16 + 8];
                mma_bf16(c0, c1, c2, c3,
                         ahi[ks][0], ahi[ks][1], ahi[ks][2], ahi[ks][3], bf0, bf1);
                mma_bf16(d0, d1, d2, d3,
                         alo[ks][0], alo[ks][1], alo[ks][2], alo[ks][3], bf0, bf1);
            }
        }
        ghp[kc][q][m * 16 + rg2]     = (c0 + d0) + (c1 + d1);
        ghp[kc][q][m * 16 + 8 + rg2] = (c2 + d2) + (c3 + d3);

        // split barrier: matvec-only warps just arrive; gate warps sync
        if (tid >= 128) {
            asm volatile("bar.arrive 1, %0;" :: "n"(REC_THREADS) : "memory");
        } else {
            asm volatile("bar.sync 1, %0;" :: "n"(REC_THREADS) : "memory");

            // ---- gates (threads 0..127): batched reduce, gate math, send ----
            float pr[4], pz[4], pn[4];
#pragma unroll
            for (int k = 0; k < 4; k++) pr[k] = ghp[k][gb][gj];
#pragma unroll
            for (int k = 0; k < 4; k++) pz[k] = ghp[k][gb][32 + gj];
#pragma unroll
            for (int k = 0; k < 4; k++) pn[k] = ghp[k][gb][64 + gj];
            const float sr_ = (pr[0] + pr[1]) + (pr[2] + pr[3]);
            const float sz_ = (pz[0] + pz[1]) + (pz[2] + pz[3]);
            const float sn_ = (pn[0] + pn[1]) + (pn[2] + pn[3]);

            const float hprev = hreg;
            const float r = sigm(gir + sr_);
            const float z = sigm(giz + sz_);
            const float n = tanh_fast(gin + r * (sn_ + bhn));
            const float hnew = (1.f - z) * n + z * hprev;
            const float hg   = wt * hnew + (1.f - wt) * hprev;
            const float hv   = (t < mylen) ? hg : hprev;
            hreg = hv;

            // split hv -> {hh, hl} bf16; gather 4 columns into one 16 B msg
            uint16_t hh16, hl16;
            asm("cvt.rn.bf16.f32 %0, %1;" : "=h"(hh16) : "f"(hv));
            const float hlr = hv - __uint_as_float((uint32_t)hh16 << 16);
            asm("cvt.rn.bf16.f32 %0, %1;" : "=h"(hl16) : "f"(hlr));
            const uint32_t own = (uint32_t)hh16 | ((uint32_t)hl16 << 16);
            const uint32_t o1 = __shfl_down_sync(0xffffffffu, own, 1);
            const uint32_t o2 = __shfl_down_sync(0xffffffffu, own, 2);
            const uint32_t o3 = __shfl_down_sync(0xffffffffu, own, 3);
            if ((gj & 3) == 0) {
                // words at dest (pairs 2p, 2p+1): {hh2_01, hl2_01, hh2_23, hl2_23}
                const uint32_t w0 = prmt(own, o1, 0x5410u);
                const uint32_t w1 = prmt(own, o1, 0x7632u);
                const uint32_t w2 = prmt(o2, o3, 0x5410u);
                const uint32_t w3 = prmt(o2, o3, 0x7632u);
                const uint32_t bofs = (uint32_t)nxt * (HXW * 4u);
                const uint32_t mofs = (uint32_t)dmb + (uint32_t)nxt * 8u;
#pragma unroll
                for (int d = 0; d < 8; d++) {
                    const uint32_t rh = rh0[d] + bofs;
                    const uint32_t rm = rh0[d] + mofs;
                    asm volatile(
                        "st.async.shared::cluster.mbarrier::complete_tx::bytes"
                        ".v4.b32 [%0], {%1, %2, %3, %4}, [%5];"
                        :: "r"(rh), "r"(w0), "r"(w1), "r"(w2), "r"(w3), "r"(rm)
                        : "memory");
                }
            }
        }
    }

    // drain final phase before exit
    {
        uint32_t mf = (uint32_t)__cvta_generic_to_shared(&mbar[Tmax & 1]);
        mbar_wait(mf, (Tmax & 1) ? ph1 : ph0);
    }
    if (tid < 128) out[(size_t)myb * H_ + col] = hreg;

    asm volatile("barrier.cluster.arrive.aligned;" ::: "memory");
    asm volatile("barrier.cluster.wait.aligned;" ::: "memory");
}

// ======================= launch =======================
extern "C" void kernel_launch(void* const* d_in, const int* in_sizes, int n_in,
                              void* d_out, int out_size)
{
    const float* x       = (const float*)d_in[0];
    const float* att     = (const float*)d_in[1];
    const int*   lengths = (const int*)  d_in[2];
    const float* W_ih    = (const float*)d_in[3];
    const float* W_hh    = (const float*)d_in[4];
    const float* b_ih    = (const float*)d_in[5];
    const float* b_hh    = (const float*)d_in[6];
    float* out = (float*)d_out;
    (void)in_sizes; (void)n_in; (void)out_size;

    dim3 ggrid(1024, 12);
    gi_gemm_wmma<<<ggrid, 256>>>(x, W_ih, lengths);
    gru_rec<<<128, REC_THREADS>>>(att, lengths, W_hh, b_hh, b_ih, out);
}

// round 15
// speedup vs baseline: 1.0723x; 1.0723x over previous
#include <cuda_runtime.h>
#include <cuda_bf16.h>
#include <mma.h>
#include <cstdint>

using namespace nvcuda;

#define B_  64
#define T_  2048
#define I_  256
#define H_  256
#define G3_ 768

// 402 MB scratch for precomputed input gates (NO bias): layout [t][b][768]
__device__ float g_Gi[(size_t)B_ * T_ * G3_];
// pre-split bf16 hi/lo operands for the Gi GEMM
__device__ __nv_bfloat16 g_xh[(size_t)B_ * T_ * I_];   // 67 MB
__device__ __nv_bfloat16 g_xl[(size_t)B_ * T_ * I_];   // 67 MB
__device__ __nv_bfloat16 g_wh[G3_ * I_];
__device__ __nv_bfloat16 g_wl[G3_ * I_];

// ======================= Phase 0: fp32 -> bf16 hi/lo split ====================
__device__ __forceinline__ void split1(float v, __nv_bfloat16& h, __nv_bfloat16& l) {
    h = __float2bfloat16(v);
    l = __float2bfloat16(v - __bfloat162float(h));
}

__global__ __launch_bounds__(256) void split_x(const float* __restrict__ src) {
    const int i = blockIdx.x * 256 + threadIdx.x;        // n4 = 8388608 exact
    float4 v = ((const float4*)src)[i];
    __nv_bfloat16 h0, h1, h2, h3, l0, l1, l2, l3;
    split1(v.x, h0, l0); split1(v.y, h1, l1);
    split1(v.z, h2, l2); split1(v.w, h3, l3);
    ((__nv_bfloat162*)g_xh)[2 * i]     = __nv_bfloat162(h0, h1);
    ((__nv_bfloat162*)g_xh)[2 * i + 1] = __nv_bfloat162(h2, h3);
    ((__nv_bfloat162*)g_xl)[2 * i]     = __nv_bfloat162(l0, l1);
    ((__nv_bfloat162*)g_xl)[2 * i + 1] = __nv_bfloat162(l2, l3);
}

__global__ __launch_bounds__(256) void split_w(const float* __restrict__ src) {
    const int i = blockIdx.x * 256 + threadIdx.x;        // n4 = 49152 exact
    float4 v = ((const float4*)src)[i];
    __nv_bfloat16 h0, h1, h2, h3, l0, l1, l2, l3;
    split1(v.x, h0, l0); split1(v.y, h1, l1);
    split1(v.z, h2, l2); split1(v.w, h3, l3);
    ((__nv_bfloat162*)g_wh)[2 * i]     = __nv_bfloat162(h0, h1);
    ((__nv_bfloat162*)g_wh)[2 * i + 1] = __nv_bfloat162(h2, h3);
    ((__nv_bfloat162*)g_wl)[2 * i]     = __nv_bfloat162(l0, l1);
    ((__nv_bfloat162*)g_wl)[2 * i + 1] = __nv_bfloat162(l2, l3);
}

// ======================= Phase 1: Gi = x @ W_ih^T  (wmma bf16 hi/lo) ==========
// R15: direct bf16 tile loads (pre-split operands), grid swapped to (n, m)
// so the 12 n-tile CTAs sharing an x tile are schedule-adjacent (L2 reuse);
// W tiles (786 KB bf16 total) are L2-resident.

#define GBK 32
#define GLD 48

__global__ __launch_bounds__(256) void gi_gemm_wmma(const int* __restrict__ lengths)
{
    const int mt    = blockIdx.y;          // 0..1023
    const int batch = mt >> 4;
    const int t0    = (mt & 15) * 128;
    if (t0 >= __ldg(&lengths[batch])) return;
    const int n0 = blockIdx.x * 64;        // 0..11 * 64

    __shared__ __nv_bfloat16 Ah[128][GLD], Al[128][GLD];
    __shared__ __nv_bfloat16 Bh[64][GLD],  Bl[64][GLD];

    const int tid  = threadIdx.x;
    const int warp = tid >> 5;
    const int wm   = warp >> 1;
    const int wn   = warp & 1;

    wmma::fragment<wmma::accumulator, 16, 16, 16, float> acc[2][2];
#pragma unroll
    for (int mi = 0; mi < 2; mi++)
#pragma unroll
        for (int ni = 0; ni < 2; ni++) wmma::fill_fragment(acc[mi][ni], 0.f);

    for (int ks = 0; ks < I_; ks += GBK) {
        // A: 128 rows x 32 cols bf16, 16 B chunks: 512 chunks, 2 per thread
#pragma unroll
        for (int j = 0; j < 2; j++) {
            const int idx = tid + j * 256;
            const int row = idx >> 2, c8 = (idx & 3) * 8;
            const size_t off = (size_t)(batch * T_ + t0 + row) * I_ + ks + c8;
            *(uint4*)&Ah[row][c8] = *(const uint4*)&g_xh[off];
            *(uint4*)&Al[row][c8] = *(const uint4*)&g_xl[off];
        }
        // B: 64 rows x 32 cols: 256 chunks, 1 per thread
        {
            const int row = tid >> 2, c8 = (tid & 3) * 8;
            const size_t off = (size_t)(n0 + row) * I_ + ks + c8;
            *(uint4*)&Bh[row][c8] = *(const uint4*)&g_wh[off];
            *(uint4*)&Bl[row][c8] = *(const uint4*)&g_wl[off];
        }
        __syncthreads();

#pragma unroll
        for (int kk = 0; kk < GBK; kk += 16) {
            wmma::fragment<wmma::matrix_a, 16, 16, 16, __nv_bfloat16,
                           wmma::row_major> ah[2], al[2];
            wmma::fragment<wmma::matrix_b, 16, 16, 16, __nv_bfloat16,
                           wmma::col_major> bh[2], bl[2];
#pragma unroll
            for (int mi = 0; mi < 2; mi++) {
                wmma::load_matrix_sync(ah[mi], &Ah[wm * 32 + mi * 16][kk], GLD);
                wmma::load_matrix_sync(al[mi], &Al[wm * 32 + mi * 16][kk], GLD);
            }
#pragma unroll
            for (int ni = 0; ni < 2; ni++) {
                wmma::load_matrix_sync(bh[ni], &Bh[wn * 32 + ni * 16][kk], GLD);
                wmma::load_matrix_sync(bl[ni], &Bl[wn * 32 + ni * 16][kk], GLD);
            }
#pragma unroll
            for (int mi = 0; mi < 2; mi++)
#pragma unroll
                for (int ni = 0; ni < 2; ni++) {
                    wmma::mma_sync(acc[mi][ni], ah[mi], bh[ni], acc[mi][ni]);
                    wmma::mma_sync(acc[mi][ni], ah[mi], bl[ni], acc[mi][ni]);
                    wmma::mma_sync(acc[mi][ni], al[mi], bh[ni], acc[mi][ni]);
                }
        }
        __syncthreads();
    }

#pragma unroll
    for (int mi = 0; mi < 2; mi++)
#pragma unroll
        for (int ni = 0; ni < 2; ni++) {
            float* dst = &g_Gi[((size_t)(t0 + wm * 32 + mi * 16) * B_ + batch) * G3_
                               + n0 + wn * 32 + ni * 16];
            wmma::store_matrix_sync(dst, acc[mi][ni], (unsigned)(B_ * G3_),
                                    wmma::mem_row_major);
        }
}

// ======================= Phase 2: recurrence (R13 exact — best measured) ======

#define REC_THREADS 768
#define EXP_TX 4096
#define HXW 1056                         // 4 batches * 264 words

__device__ __forceinline__ float sigm(float v) { return 1.f / (1.f + __expf(-v)); }
__device__ __forceinline__ float tanh_fast(float u) {
    const float t = __expf(-2.f * fabsf(u));
    const float m = (1.f - t) / (1.f + t);
    return copysignf(m, u);
}
__device__ __forceinline__ uint32_t split_pack(float2 v, uint32_t& lo_pack) {
    uint16_t h0, h1, l0, l1;
    asm("cvt.rn.bf16.f32 %0, %1;" : "=h"(h0) : "f"(v.x));
    asm("cvt.rn.bf16.f32 %0, %1;" : "=h"(h1) : "f"(v.y));
    float r0 = v.x - __uint_as_float((uint32_t)h0 << 16);
    float r1 = v.y - __uint_as_float((uint32_t)h1 << 16);
    asm("cvt.rn.bf16.f32 %0, %1;" : "=h"(l0) : "f"(r0));
    asm("cvt.rn.bf16.f32 %0, %1;" : "=h"(l1) : "f"(r1));
    lo_pack = (uint32_t)l0 | ((uint32_t)l1 << 16);
    return (uint32_t)h0 | ((uint32_t)h1 << 16);
}
__device__ __forceinline__ void mma_bf16(
    float& c0, float& c1, float& c2, float& c3,
    uint32_t a0, uint32_t a1, uint32_t a2, uint32_t a3,
    uint32_t b0, uint32_t b1)
{
    asm("mma.sync.aligned.m16n8k16.row.col.f32.bf16.bf16.f32 "
        "{%0,%1,%2,%3}, {%4,%5,%6,%7}, {%8,%9}, {%0,%1,%2,%3};"
        : "+f"(c0), "+f"(c1), "+f"(c2), "+f"(c3)
        : "r"(a0), "r"(a1), "r"(a2), "r"(a3), "r"(b0), "r"(b1));
}
__device__ __forceinline__ uint32_t prmt(uint32_t a, uint32_t b, uint32_t s) {
    uint32_t d;
    asm("prmt.b32 %0, %1, %2, %3;" : "=r"(d) : "r"(a), "r"(b), "r"(s));
    return d;
}
__device__ __forceinline__ void mbar_wait(uint32_t mbar, uint32_t parity) {
    uint32_t done;
    asm volatile(
        "{\n\t.reg .pred p;\n\t"
        "mbarrier.try_wait.parity.acquire.cta.shared::cta.b64 p, [%1], %2;\n\t"
        "selp.b32 %0, 1, 0, p;\n\t}"
        : "=r"(done) : "r"(mbar), "r"(parity) : "memory");
    while (!done) {
        asm volatile(
            "{\n\t.reg .pred p;\n\t"
            "mbarrier.try_wait.parity.acquire.cta.shared::cta.b64 p, [%1], %2, 0x989680;\n\t"
            "selp.b32 %0, 1, 0, p;\n\t}"
            : "=r"(done) : "r"(mbar), "r"(parity) : "memory");
    }
}

__global__ void __cluster_dims__(8, 1, 1) __launch_bounds__(REC_THREADS, 1)
gru_rec(const float* __restrict__ att, const int* __restrict__ lengths,
        const float* __restrict__ W_hh, const float* __restrict__ b_hh,
        const float* __restrict__ b_ih, float* __restrict__ out)
{
    __shared__ uint32_t hx[2][HXW];       // [buf][b*264 + pair*2 + sel]
    __shared__ float ghp[4][4][104];      // [kc][batch][row 0..95, pad 104]
    __shared__ alignas(8) unsigned long long mbar[2];

    uint32_t rank;
    asm("mov.u32 %0, %%cluster_ctarank;" : "=r"(rank));
    const int cid = blockIdx.x >> 3;
    const int b0  = cid * 4;

    const int tid  = threadIdx.x;
    const int warp = tid >> 5;
    const int lane = tid & 31;
    const int m    = warp >> 2;           // m-tile 0..5
    const int kc   = warp & 3;            // k slice 0..3
    const int q    = lane & 3;
    const int rg2  = lane >> 2;           // 0..7

    // ---- loop-invariant A fragments (W_hh hi/lo) ----
    const int row0 = m * 16 + rg2;                               // local row
    const int grow = (row0 >> 5) * 256 + (int)rank * 32 + (row0 & 31);
    uint32_t ahi[4][4], alo[4][4];
#pragma unroll
    for (int ks = 0; ks < 4; ks++) {
        const int k0 = kc * 64 + ks * 16 + q * 2;
        float2 v00 = *(const float2*)&W_hh[(size_t)grow * H_ + k0];
        float2 v10 = *(const float2*)&W_hh[(size_t)(grow + 8) * H_ + k0];
        float2 v01 = *(const float2*)&W_hh[(size_t)grow * H_ + k0 + 8];
        float2 v11 = *(const float2*)&W_hh[(size_t)(grow + 8) * H_ + k0 + 8];
        ahi[ks][0] = split_pack(v00, alo[ks][0]);
        ahi[ks][1] = split_pack(v10, alo[ks][1]);
        ahi[ks][2] = split_pack(v01, alo[ks][2]);
        ahi[ks][3] = split_pack(v11, alo[ks][3]);
    }

    // ---- zero h buffer 0, init mbarriers ----
    for (int i = tid; i < HXW; i += REC_THREADS) hx[0][i] = 0u;
    if (tid < 2) {
        uint32_t mb = (uint32_t)__cvta_generic_to_shared(&mbar[tid]);
        asm volatile("mbarrier.init.shared.b64 [%0], 1;" :: "r"(mb) : "memory");
    }

    // ---- gate constants (threads 0..127: gb = tid>>5, gj = tid&31) ----
    const int gb   = tid >> 5;
    const int gj   = tid & 31;
    const int col  = (int)rank * 32 + gj;
    const int myb  = b0 + gb;
    float bcr = 0.f, bcz = 0.f, bcn = 0.f, bhn = 0.f;
    int mylen = 0;
    if (tid < 128) {
        bcr = b_ih[col] + b_hh[col];
        bcz = b_ih[256 + col] + b_hh[256 + col];
        bcn = b_ih[512 + col];
        bhn = b_hh[512 + col];
        mylen = lengths[myb];
    }
    float hreg = 0.f;
    const int Tmax = max(max(__ldg(&lengths[b0]),     __ldg(&lengths[b0 + 1])),
                         max(__ldg(&lengths[b0 + 2]), __ldg(&lengths[b0 + 3])));

    // ---- lane constants for B-fragment loads ----
    const int wb = (lane >> 3) * 264 + kc * 64 + q * 2 + ((lane >> 2) & 1);

    // ---- hoisted peer addresses (sending lanes: tid<128, even gj) ----
    uint32_t rh0[8];
    int32_t  dmb = 0;
    {
        const int pair = (int)rank * 16 + (gj >> 1);
        uint32_t lh0 = (uint32_t)__cvta_generic_to_shared(&hx[0][gb * 264 + pair * 2]);
        uint32_t lm0 = (uint32_t)__cvta_generic_to_shared(&mbar[0]);
        dmb = (int32_t)(lm0 - lh0);
#pragma unroll
        for (int d = 0; d < 8; d++)
            asm("mapa.shared::cluster.u32 %0, %1, %2;"
                : "=r"(rh0[d]) : "r"(lh0), "r"(d));
    }

    __syncthreads();
    asm volatile("barrier.cluster.arrive.aligned;" ::: "memory");
    asm volatile("barrier.cluster.wait.aligned;" ::: "memory");

    uint32_t ph0 = 0, ph1 = 0;

    for (int t = 0; t < Tmax; t++) {
        const int cur = t & 1, nxt = cur ^ 1;

        // arm next buffer (non-gate warp)
        if (tid == 256) {
            uint32_t mn = (uint32_t)__cvta_generic_to_shared(&mbar[nxt]);
            asm volatile("mbarrier.arrive.expect_tx.shared.b64 _, [%0], %1;"
                         :: "r"(mn), "n"(EXP_TX) : "memory");
        }

        // gi prefetch + bias fold (no h dependency)
        float gir = 0.f, giz = 0.f, gin = 0.f, wt = 0.f;
        if (tid < 128) {
            const size_t base = ((size_t)t * B_ + myb) * G3_;
            gir = __ldg(&g_Gi[base + col]) + bcr;
            giz = __ldg(&g_Gi[base + 256 + col]) + bcz;
            gin = __ldg(&g_Gi[base + 512 + col]) + bcn;
            wt  = __ldg(&att[(size_t)myb * T_ + t]);
        }

        if (t > 0) {
            uint32_t mc = (uint32_t)__cvta_generic_to_shared(&mbar[cur]);
            mbar_wait(mc, cur ? ph1 : ph0);
            if (cur) ph1 ^= 1; else ph0 ^= 1;
        }

        // ---- HMMA matvec: dual independent chains (hi->c, lo->d) ----
        float c0 = 0.f, c1 = 0.f, c2 = 0.f, c3 = 0.f;
        float d0 = 0.f, d1 = 0.f, d2 = 0.f, d3 = 0.f;
        {
            const uint32_t* hxc = hx[cur];
#pragma unroll
            for (int ks = 0; ks < 4; ks++) {
                const uint32_t bf0 = hxc[wb + ks * 16];
                const uint32_t bf1 = hxc[wb + ks * 16 + 8];
                mma_bf16(c0, c1, c2, c3,
                         ahi[ks][0], ahi[ks][1], ahi[ks][2], ahi[ks][3], bf0, bf1);
                mma_bf16(d0, d1, d2, d3,
                         alo[ks][0], alo[ks][1], alo[ks][2], alo[ks][3], bf0, bf1);
            }
        }
        ghp[kc][q][m * 16 + rg2]     = (c0 + d0) + (c1 + d1);
        ghp[kc][q][m * 16 + 8 + rg2] = (c2 + d2) + (c3 + d3);

        // split barrier: matvec-only warps just arrive; gate warps sync
        if (tid >= 128) {
            asm volatile("bar.arrive 1, %0;" :: "n"(REC_THREADS) : "memory");
        } else {
            asm volatile("bar.sync 1, %0;" :: "n"(REC_THREADS) : "memory");

            // ---- gates (threads 0..127): batched reduce, gate math, send ----
            float pr[4], pz[4], pn[4];
#pragma unroll
            for (int k = 0; k < 4; k++) pr[k] = ghp[k][gb][gj];
#pragma unroll
            for (int k = 0; k < 4; k++) pz[k] = ghp[k][gb][32 + gj];
#pragma unroll
            for (int k = 0; k < 4; k++) pn[k] = ghp[k][gb][64 + gj];
            const float sr_ = (pr[0] + pr[1]) + (pr[2] + pr[3]);
            const float sz_ = (pz[0] + pz[1]) + (pz[2] + pz[3]);
            const float sn_ = (pn[0] + pn[1]) + (pn[2] + pn[3]);

            const float hprev = hreg;
            const float r = sigm(gir + sr_);
            const float z = sigm(giz + sz_);
            const float n = tanh_fast(gin + r * (sn_ + bhn));
            const float hnew = (1.f - z) * n + z * hprev;
            const float hg   = wt * hnew + (1.f - wt) * hprev;
            const float hv   = (t < mylen) ? hg : hprev;
            hreg = hv;

            // split hv -> {hh, hl} bf16, pack with neighbor column
            uint16_t hh16, hl16;
            asm("cvt.rn.bf16.f32 %0, %1;" : "=h"(hh16) : "f"(hv));
            const float hlr = hv - __uint_as_float((uint32_t)hh16 << 16);
            asm("cvt.rn.bf16.f32 %0, %1;" : "=h"(hl16) : "f"(hlr));
            const uint32_t own = (uint32_t)hh16 | ((uint32_t)hl16 << 16);
            const uint32_t oth = __shfl_down_sync(0xffffffffu, own, 1);
            if ((gj & 1) == 0) {
                const uint32_t hh2 = prmt(own, oth, 0x5410u);
                const uint32_t hl2 = prmt(own, oth, 0x7632u);
                unsigned long long pk;
                asm("mov.b64 %0, {%1, %2};" : "=l"(pk) : "r"(hh2), "r"(hl2));
                const uint32_t bofs = (uint32_t)nxt * (HXW * 4u);
                const uint32_t mofs = (uint32_t)dmb + (uint32_t)nxt * 8u;
#pragma unroll
                for (int d = 0; d < 8; d++) {
                    const uint32_t rh = rh0[d] + bofs;
                    const uint32_t rm = rh0[d] + mofs;
                    asm volatile(
                        "st.async.shared::cluster.mbarrier::complete_tx::bytes.b64 "
                        "[%0], %1, [%2];"
                        :: "r"(rh), "l"(pk), "r"(rm) : "memory");
                }
            }
        }
    }

    // drain final phase before exit
    {
        uint32_t mf = (uint32_t)__cvta_generic_to_shared(&mbar[Tmax & 1]);
        mbar_wait(mf, (Tmax & 1) ? ph1 : ph0);
    }
    if (tid < 128) out[(size_t)myb * H_ + col] = hreg;

    asm volatile("barrier.cluster.arrive.aligned;" ::: "memory");
    asm volatile("barrier.cluster.wait.aligned;" ::: "memory");
}

// ======================= launch =======================
extern "C" void kernel_launch(void* const* d_in, const int* in_sizes, int n_in,
                              void* d_out, int out_size)
{
    const float* x       = (const float*)d_in[0];
    const float* att     = (const float*)d_in[1];
    const int*   lengths = (const int*)  d_in[2];
    const float* W_ih    = (const float*)d_in[3];
    const float* W_hh    = (const float*)d_in[4];
    const float* b_ih    = (const float*)d_in[5];
    const float* b_hh    = (const float*)d_in[6];
    float* out = (float*)d_out;
    (void)in_sizes; (void)n_in; (void)out_size;

    split_x<<<(B_ * T_ * I_) / 4 / 256, 256>>>(x);            // 32768 blocks
    split_w<<<(G3_ * I_) / 4 / 256, 256>>>(W_ih);             // 192 blocks
    gi_gemm_wmma<<<dim3(12, 1024), 256>>>(lengths);
    gru_rec<<<128, REC_THREADS>>>(att, lengths, W_hh, b_hh, b_ih, out);
}

// round 16
// speedup vs baseline: 1.2780x; 1.1919x over previous
#include <cuda_runtime.h>
#include <cuda_bf16.h>
#include <mma.h>
#include <cstdint>

using namespace nvcuda;

#define B_  64
#define T_  2048
#define I_  256
#define H_  256
#define G3_ 768

// 402 MB scratch for precomputed input gates (NO bias): layout [t][b][768]
__device__ float g_Gi[(size_t)B_ * T_ * G3_];

// ======================= Phase 1: Gi = x @ W_ih^T  (wmma bf16 hi/lo) ==========
// R13 gemm (in-kernel hi/lo convert) + R15's grid swap (n-tiles adjacent in
// schedule for L2 reuse of the x tile).

#define GBK 32
#define GLD 48

__global__ __launch_bounds__(256) void gi_gemm_wmma(
    const float* __restrict__ x, const float* __restrict__ W_ih,
    const int* __restrict__ lengths)
{
    const int mt    = blockIdx.y;          // 0..1023
    const int batch = mt >> 4;
    const int t0    = (mt & 15) * 128;
    if (t0 >= __ldg(&lengths[batch])) return;
    const int n0 = blockIdx.x * 64;        // 0..11

    __shared__ __nv_bfloat16 Ah[128][GLD], Al[128][GLD];
    __shared__ __nv_bfloat16 Bh[64][GLD],  Bl[64][GLD];

    const int tid  = threadIdx.x;
    const int warp = tid >> 5;
    const int wm   = warp >> 1;
    const int wn   = warp & 1;

    wmma::fragment<wmma::accumulator, 16, 16, 16, float> acc[2][2];
#pragma unroll
    for (int mi = 0; mi < 2; mi++)
#pragma unroll
        for (int ni = 0; ni < 2; ni++) wmma::fill_fragment(acc[mi][ni], 0.f);

    for (int ks = 0; ks < I_; ks += GBK) {
#pragma unroll
        for (int j = 0; j < 4; j++) {
            const int idx = tid + j * 256;
            const int row = idx >> 3, c = (idx & 7) * 4;
            float4 v = *(const float4*)&x[(size_t)(batch * T_ + t0 + row) * I_ + ks + c];
            __nv_bfloat16 hx = __float2bfloat16(v.x);
            __nv_bfloat16 hy = __float2bfloat16(v.y);
            __nv_bfloat16 hz = __float2bfloat16(v.z);
            __nv_bfloat16 hw = __float2bfloat16(v.w);
            *(__nv_bfloat162*)&Ah[row][c]     = __nv_bfloat162(hx, hy);
            *(__nv_bfloat162*)&Ah[row][c + 2] = __nv_bfloat162(hz, hw);
            *(__nv_bfloat162*)&Al[row][c] = __nv_bfloat162(
                __float2bfloat16(v.x - __bfloat162float(hx)),
                __float2bfloat16(v.y - __bfloat162float(hy)));
            *(__nv_bfloat162*)&Al[row][c + 2] = __nv_bfloat162(
                __float2bfloat16(v.z - __bfloat162float(hz)),
                __float2bfloat16(v.w - __bfloat162float(hw)));
        }
#pragma unroll
        for (int j = 0; j < 2; j++) {
            const int idx = tid + j * 256;
            const int row = idx >> 3, c = (idx & 7) * 4;
            float4 v = *(const float4*)&W_ih[(size_t)(n0 + row) * I_ + ks + c];
            __nv_bfloat16 hx = __float2bfloat16(v.x);
            __nv_bfloat16 hy = __float2bfloat16(v.y);
            __nv_bfloat16 hz = __float2bfloat16(v.z);
            __nv_bfloat16 hw = __float2bfloat16(v.w);
            *(__nv_bfloat162*)&Bh[row][c]     = __nv_bfloat162(hx, hy);
            *(__nv_bfloat162*)&Bh[row][c + 2] = __nv_bfloat162(hz, hw);
            *(__nv_bfloat162*)&Bl[row][c] = __nv_bfloat162(
                __float2bfloat16(v.x - __bfloat162float(hx)),
                __float2bfloat16(v.y - __bfloat162float(hy)));
            *(__nv_bfloat162*)&Bl[row][c + 2] = __nv_bfloat162(
                __float2bfloat16(v.z - __bfloat162float(hz)),
                __float2bfloat16(v.w - __bfloat162float(hw)));
        }
        __syncthreads();

#pragma unroll
        for (int kk = 0; kk < GBK; kk += 16) {
            wmma::fragment<wmma::matrix_a, 16, 16, 16, __nv_bfloat16,
                           wmma::row_major> ah[2], al[2];
            wmma::fragment<wmma::matrix_b, 16, 16, 16, __nv_bfloat16,
                           wmma::col_major> bh[2], bl[2];
#pragma unroll
            for (int mi = 0; mi < 2; mi++) {
                wmma::load_matrix_sync(ah[mi], &Ah[wm * 32 + mi * 16][kk], GLD);
                wmma::load_matrix_sync(al[mi], &Al[wm * 32 + mi * 16][kk], GLD);
            }
#pragma unroll
            for (int ni = 0; ni < 2; ni++) {
                wmma::load_matrix_sync(bh[ni], &Bh[wn * 32 + ni * 16][kk], GLD);
                wmma::load_matrix_sync(bl[ni], &Bl[wn * 32 + ni * 16][kk], GLD);
            }
#pragma unroll
            for (int mi = 0; mi < 2; mi++)
#pragma unroll
                for (int ni = 0; ni < 2; ni++) {
                    wmma::mma_sync(acc[mi][ni], ah[mi], bh[ni], acc[mi][ni]);
                    wmma::mma_sync(acc[mi][ni], ah[mi], bl[ni], acc[mi][ni]);
                    wmma::mma_sync(acc[mi][ni], al[mi], bh[ni], acc[mi][ni]);
                }
        }
        __syncthreads();
    }

#pragma unroll
    for (int mi = 0; mi < 2; mi++)
#pragma unroll
        for (int ni = 0; ni < 2; ni++) {
            float* dst = &g_Gi[((size_t)(t0 + wm * 32 + mi * 16) * B_ + batch) * G3_
                               + n0 + wn * 32 + ni * 16];
            wmma::store_matrix_sync(dst, acc[mi][ni], (unsigned)(B_ * G3_),
                                    wmma::mem_row_major);
        }
}

// ======================= Phase 2: recurrence (HMMA matvec) ====================
// R13 structure. R16 change: gi/att prefetch distance extended to ONE FULL
// STEP (loads for t+1 issued at top of step t, consumed at t+1's gate phase)
// — hides the ~600-1000 cyc DRAM latency of the streaming g_Gi buffer that
// was partially exposed in the serial gate tail. mapa un-hoisted (in-loop)
// to free the register budget for the prefetch double-buffer.

#define REC_THREADS 768
#define EXP_TX 4096
#define HXW 1056                         // 4 batches * 264 words

__device__ __forceinline__ float sigm(float v) { return 1.f / (1.f + __expf(-v)); }
__device__ __forceinline__ float tanh_fast(float u) {
    const float t = __expf(-2.f * fabsf(u));
    const float m = (1.f - t) / (1.f + t);
    return copysignf(m, u);
}
__device__ __forceinline__ uint32_t split_pack(float2 v, uint32_t& lo_pack) {
    uint16_t h0, h1, l0, l1;
    asm("cvt.rn.bf16.f32 %0, %1;" : "=h"(h0) : "f"(v.x));
    asm("cvt.rn.bf16.f32 %0, %1;" : "=h"(h1) : "f"(v.y));
    float r0 = v.x - __uint_as_float((uint32_t)h0 << 16);
    float r1 = v.y - __uint_as_float((uint32_t)h1 << 16);
    asm("cvt.rn.bf16.f32 %0, %1;" : "=h"(l0) : "f"(r0));
    asm("cvt.rn.bf16.f32 %0, %1;" : "=h"(l1) : "f"(r1));
    lo_pack = (uint32_t)l0 | ((uint32_t)l1 << 16);
    return (uint32_t)h0 | ((uint32_t)h1 << 16);
}
__device__ __forceinline__ void mma_bf16(
    float& c0, float& c1, float& c2, float& c3,
    uint32_t a0, uint32_t a1, uint32_t a2, uint32_t a3,
    uint32_t b0, uint32_t b1)
{
    asm("mma.sync.aligned.m16n8k16.row.col.f32.bf16.bf16.f32 "
        "{%0,%1,%2,%3}, {%4,%5,%6,%7}, {%8,%9}, {%0,%1,%2,%3};"
        : "+f"(c0), "+f"(c1), "+f"(c2), "+f"(c3)
        : "r"(a0), "r"(a1), "r"(a2), "r"(a3), "r"(b0), "r"(b1));
}
__device__ __forceinline__ uint32_t prmt(uint32_t a, uint32_t b, uint32_t s) {
    uint32_t d;
    asm("prmt.b32 %0, %1, %2, %3;" : "=r"(d) : "r"(a), "r"(b), "r"(s));
    return d;
}
__device__ __forceinline__ void mbar_wait(uint32_t mbar, uint32_t parity) {
    uint32_t done;
    asm volatile(
        "{\n\t.reg .pred p;\n\t"
        "mbarrier.try_wait.parity.acquire.cta.shared::cta.b64 p, [%1], %2;\n\t"
        "selp.b32 %0, 1, 0, p;\n\t}"
        : "=r"(done) : "r"(mbar), "r"(parity) : "memory");
    while (!done) {
        asm volatile(
            "{\n\t.reg .pred p;\n\t"
            "mbarrier.try_wait.parity.acquire.cta.shared::cta.b64 p, [%1], %2, 0x989680;\n\t"
            "selp.b32 %0, 1, 0, p;\n\t}"
            : "=r"(done) : "r"(mbar), "r"(parity) : "memory");
    }
}

__global__ void __cluster_dims__(8, 1, 1) __launch_bounds__(REC_THREADS, 1)
gru_rec(const float* __restrict__ att, const int* __restrict__ lengths,
        const float* __restrict__ W_hh, const float* __restrict__ b_hh,
        const float* __restrict__ b_ih, float* __restrict__ out)
{
    __shared__ uint32_t hx[2][HXW];       // [buf][b*264 + pair*2 + sel]
    __shared__ float ghp[4][4][104];      // [kc][batch][row 0..95, pad 104]
    __shared__ alignas(8) unsigned long long mbar[2];

    uint32_t rank;
    asm("mov.u32 %0, %%cluster_ctarank;" : "=r"(rank));
    const int cid = blockIdx.x >> 3;
    const int b0  = cid * 4;

    const int tid  = threadIdx.x;
    const int warp = tid >> 5;
    const int lane = tid & 31;
    const int m    = warp >> 2;           // m-tile 0..5
    const int kc   = warp & 3;            // k slice 0..3
    const int q    = lane & 3;
    const int rg2  = lane >> 2;           // 0..7

    // ---- loop-invariant A fragments (W_hh hi/lo) ----
    const int row0 = m * 16 + rg2;                               // local row
    const int grow = (row0 >> 5) * 256 + (int)rank * 32 + (row0 & 31);
    uint32_t ahi[4][4], alo[4][4];
#pragma unroll
    for (int ks = 0; ks < 4; ks++) {
        const int k0 = kc * 64 + ks * 16 + q * 2;
        float2 v00 = *(const float2*)&W_hh[(size_t)grow * H_ + k0];
        float2 v10 = *(const float2*)&W_hh[(size_t)(grow + 8) * H_ + k0];
        float2 v01 = *(const float2*)&W_hh[(size_t)grow * H_ + k0 + 8];
        float2 v11 = *(const float2*)&W_hh[(size_t)(grow + 8) * H_ + k0 + 8];
        ahi[ks][0] = split_pack(v00, alo[ks][0]);
        ahi[ks][1] = split_pack(v10, alo[ks][1]);
        ahi[ks][2] = split_pack(v01, alo[ks][2]);
        ahi[ks][3] = split_pack(v11, alo[ks][3]);
    }

    // ---- zero h buffer 0, init mbarriers ----
    for (int i = tid; i < HXW; i += REC_THREADS) hx[0][i] = 0u;
    if (tid < 2) {
        uint32_t mb = (uint32_t)__cvta_generic_to_shared(&mbar[tid]);
        asm volatile("mbarrier.init.shared.b64 [%0], 1;" :: "r"(mb) : "memory");
    }

    // ---- gate constants (threads 0..127: gb = tid>>5, gj = tid&31) ----
    const int gb   = tid >> 5;
    const int gj   = tid & 31;
    const int col  = (int)rank * 32 + gj;
    const int myb  = b0 + gb;
    float bcr = 0.f, bcz = 0.f, bcn = 0.f, bhn = 0.f;
    int mylen = 0;
    if (tid < 128) {
        bcr = b_ih[col] + b_hh[col];
        bcz = b_ih[256 + col] + b_hh[256 + col];
        bcn = b_ih[512 + col];
        bhn = b_hh[512 + col];
        mylen = lengths[myb];
    }
    float hreg = 0.f;
    const int Tmax = max(max(__ldg(&lengths[b0]),     __ldg(&lengths[b0 + 1])),
                         max(__ldg(&lengths[b0 + 2]), __ldg(&lengths[b0 + 3])));

    // ---- lane constants for B-fragment loads ----
    const int wb = (lane >> 3) * 264 + kc * 64 + q * 2 + ((lane >> 2) & 1);
    const int pair = (int)rank * 16 + (gj >> 1);   // send slot (gate lanes)

    // ---- gi/att prefetch pipeline: preload step 0 (raw, bias at consume) ----
    float gir = 0.f, giz = 0.f, gin = 0.f, wt = 0.f;
    if (tid < 128) {
        const size_t base0 = (size_t)myb * G3_;    // t = 0
        gir = __ldg(&g_Gi[base0 + col]);
        giz = __ldg(&g_Gi[base0 + 256 + col]);
        gin = __ldg(&g_Gi[base0 + 512 + col]);
        wt  = __ldg(&att[(size_t)myb * T_]);
    }

    __syncthreads();
    asm volatile("barrier.cluster.arrive.aligned;" ::: "memory");
    asm volatile("barrier.cluster.wait.aligned;" ::: "memory");

    uint32_t ph0 = 0, ph1 = 0;

    for (int t = 0; t < Tmax; t++) {
        const int cur = t & 1, nxt = cur ^ 1;

        // arm next buffer (non-gate warp)
        if (tid == 256) {
            uint32_t mn = (uint32_t)__cvta_generic_to_shared(&mbar[nxt]);
            asm volatile("mbarrier.arrive.expect_tx.shared.b64 _, [%0], %1;"
                         :: "r"(mn), "n"(EXP_TX) : "memory");
        }

        // prefetch gi/att for t+1 (consumed NEXT step -> full-step latency hide)
        float girn = 0.f, gizn = 0.f, ginn = 0.f, wtn = 0.f;
        if (tid < 128) {
            const int tn = (t + 1 < Tmax) ? t + 1 : t;
            const size_t basen = ((size_t)tn * B_ + myb) * G3_;
            girn = __ldg(&g_Gi[basen + col]);
            gizn = __ldg(&g_Gi[basen + 256 + col]);
            ginn = __ldg(&g_Gi[basen + 512 + col]);
            wtn  = __ldg(&att[(size_t)myb * T_ + tn]);
        }

        if (t > 0) {
            uint32_t mc = (uint32_t)__cvta_generic_to_shared(&mbar[cur]);
            mbar_wait(mc, cur ? ph1 : ph0);
            if (cur) ph1 ^= 1; else ph0 ^= 1;
        }

        // ---- HMMA matvec: dual independent chains (hi->c, lo->d) ----
        float c0 = 0.f, c1 = 0.f, c2 = 0.f, c3 = 0.f;
        float d0 = 0.f, d1 = 0.f, d2 = 0.f, d3 = 0.f;
        {
            const uint32_t* hxc = hx[cur];
#pragma unroll
            for (int ks = 0; ks < 4; ks++) {
                const uint32_t bf0 = hxc[wb + ks * 16];
                const uint32_t bf1 = hxc[wb + ks * 16 + 8];
                mma_bf16(c0, c1, c2, c3,
                         ahi[ks][0], ahi[ks][1], ahi[ks][2], ahi[ks][3], bf0, bf1);
                mma_bf16(d0, d1, d2, d3,
                         alo[ks][0], alo[ks][1], alo[ks][2], alo[ks][3], bf0, bf1);
            }
        }
        ghp[kc][q][m * 16 + rg2]     = (c0 + d0) + (c1 + d1);
        ghp[kc][q][m * 16 + 8 + rg2] = (c2 + d2) + (c3 + d3);

        // split barrier: matvec-only warps just arrive; gate warps sync
        if (tid >= 128) {
            asm volatile("bar.arrive 1, %0;" :: "n"(REC_THREADS) : "memory");
        } else {
            asm volatile("bar.sync 1, %0;" :: "n"(REC_THREADS) : "memory");

            // ---- gates (threads 0..127): batched reduce, gate math, send ----
            float pr[4], pz[4], pn[4];
#pragma unroll
            for (int k = 0; k < 4; k++) pr[k] = ghp[k][gb][gj];
#pragma unroll
            for (int k = 0; k < 4; k++) pz[k] = ghp[k][gb][32 + gj];
#pragma unroll
            for (int k = 0; k < 4; k++) pn[k] = ghp[k][gb][64 + gj];
            const float sr_ = (pr[0] + pr[1]) + (pr[2] + pr[3]);
            const float sz_ = (pz[0] + pz[1]) + (pz[2] + pz[3]);
            const float sn_ = (pn[0] + pn[1]) + (pn[2] + pn[3]);

            const float hprev = hreg;
            const float r = sigm((gir + bcr) + sr_);
            const float z = sigm((giz + bcz) + sz_);
            const float n = tanh_fast((gin + bcn) + r * (sn_ + bhn));
            const float hnew = (1.f - z) * n + z * hprev;
            const float hg   = wt * hnew + (1.f - wt) * hprev;
            const float hv   = (t < mylen) ? hg : hprev;
            hreg = hv;

            // split hv -> {hh, hl} bf16, pack with neighbor column
            uint16_t hh16, hl16;
            asm("cvt.rn.bf16.f32 %0, %1;" : "=h"(hh16) : "f"(hv));
            const float hlr = hv - __uint_as_float((uint32_t)hh16 << 16);
            asm("cvt.rn.bf16.f32 %0, %1;" : "=h"(hl16) : "f"(hlr));
            const uint32_t own = (uint32_t)hh16 | ((uint32_t)hl16 << 16);
            const uint32_t oth = __shfl_down_sync(0xffffffffu, own, 1);
            if ((gj & 1) == 0) {
                const uint32_t hh2 = prmt(own, oth, 0x5410u);
                const uint32_t hl2 = prmt(own, oth, 0x7632u);
                unsigned long long pk;
                asm("mov.b64 %0, {%1, %2};" : "=l"(pk) : "r"(hh2), "r"(hl2));
                uint32_t lh = (uint32_t)__cvta_generic_to_shared(
                    &hx[nxt][gb * 264 + pair * 2]);
                uint32_t lm = (uint32_t)__cvta_generic_to_shared(&mbar[nxt]);
#pragma unroll
                for (int d = 0; d < 8; d++) {
                    uint32_t rh, rm;
                    asm volatile("mapa.shared::cluster.u32 %0, %1, %2;"
                                 : "=r"(rh) : "r"(lh), "r"(d));
                    asm volatile("mapa.shared::cluster.u32 %0, %1, %2;"
                                 : "=r"(rm) : "r"(lm), "r"(d));
                    asm volatile(
                        "st.async.shared::cluster.mbarrier::complete_tx::bytes.b64 "
                        "[%0], %1, [%2];"
                        :: "r"(rh), "l"(pk), "r"(rm) : "memory");
                }
            }
            // rotate the prefetch pipeline
            gir = girn; giz = gizn; gin = ginn; wt = wtn;
        }
    }

    // drain final phase before exit
    {
        uint32_t mf = (uint32_t)__cvta_generic_to_shared(&mbar[Tmax & 1]);
        mbar_wait(mf, (Tmax & 1) ? ph1 : ph0);
    }
    if (tid < 128) out[(size_t)myb * H_ + col] = hreg;

    asm volatile("barrier.cluster.arrive.aligned;" ::: "memory");
    asm volatile("barrier.cluster.wait.aligned;" ::: "memory");
}

// ======================= launch =======================
extern "C" void kernel_launch(void* const* d_in, const int* in_sizes, int n_in,
                              void* d_out, int out_size)
{
    const float* x       = (const float*)d_in[0];
    const float* att     = (const float*)d_in[1];
    const int*   lengths = (const int*)  d_in[2];
    const float* W_ih    = (const float*)d_in[3];
    const float* W_hh    = (const float*)d_in[4];
    const float* b_ih    = (const float*)d_in[5];
    const float* b_hh    = (const float*)d_in[6];
    float* out = (float*)d_out;
    (void)in_sizes; (void)n_in; (void)out_size;

    gi_gemm_wmma<<<dim3(12, 1024), 256>>>(x, W_ih, lengths);
    gru_rec<<<128, REC_THREADS>>>(att, lengths, W_hh, b_hh, b_ih, out);
}